// round 17
// baseline (speedup 1.0000x reference)
#include <cuda_runtime.h>
#include <math.h>

#define BATCH   4096
#define NBLK    66
#define NPAIR   33       // n-pairs
#define XDIM    264      // 66 * 4
#define PHI_H   256
#define PHI_OUT 64
#define RHO_H   256
#define WARPS_PER_BLOCK 4
#define PAIRS           2
#define ROWS_PER_BLOCK  4                    // 2 rows per warp-pair
#define NBLOCKS (BATCH / ROWS_PER_BLOCK)     // 1024

typedef unsigned long long ull;

// Global scratch: cross-batch max key + completion counter (self-resetting).
__device__ unsigned g_maxkey = 0u;
__device__ unsigned g_done   = 0u;

// ---- packed f32x2 helpers ----
__device__ __forceinline__ ull ffma2(ull a, ull b, ull c) {
    ull d; asm("fma.rn.f32x2 %0, %1, %2, %3;" : "=l"(d) : "l"(a), "l"(b), "l"(c)); return d;
}
__device__ __forceinline__ ull add2(ull a, ull b) {
    ull d; asm("add.rn.f32x2 %0, %1, %2;" : "=l"(d) : "l"(a), "l"(b)); return d;
}
__device__ __forceinline__ ull pack2(float lo, float hi) {
    ull v; asm("mov.b64 %0, {%1, %2};" : "=l"(v) : "f"(lo), "f"(hi)); return v;
}
__device__ __forceinline__ float2 unpack2(ull v) {
    float2 r; asm("mov.b64 {%0, %1}, %2;" : "=f"(r.x), "=f"(r.y) : "l"(v)); return r;
}
__device__ __forceinline__ ull dup2(float v) { return pack2(v, v); }

// Monotonic float->uint key.
__device__ __forceinline__ unsigned fkey(float f) {
    unsigned b = __float_as_uint(f);
    return (b & 0x80000000u) ? ~b : (b | 0x80000000u);
}
__device__ __forceinline__ float kinv(unsigned k) {
    unsigned b = (k & 0x80000000u) ? (k & 0x7fffffffu) : ~k;
    return __uint_as_float(b);
}

__global__ __launch_bounds__(32 * WARPS_PER_BLOCK, 6) void bn_main_kernel(
    const float* __restrict__ x,
    const float* __restrict__ pw1, const float* __restrict__ pb1,
    const float* __restrict__ pw2, const float* __restrict__ pb2,
    const float* __restrict__ rw1, const float* __restrict__ rb1,
    const float* __restrict__ rw2, const float* __restrict__ rb2,
    float* __restrict__ out)
{
    // x staged SoA: xsT[pair][row][comp][n] -> LDS.64 at [comp][2*np] gives the
    // natural packed operand (s_n, s_{n+1}) with ZERO dup-MOVs in the hot loop.
    __shared__ __align__(16) float xsT[PAIRS][2][4][68];   // 68 = 66 + pad (8B-stride safe)
    // ubuf time-multiplexed: phase1 = H floats (Hsf[row*256+j], 2KB of 4KB/pair);
    // phase2 = rho partials ubuf[p][member][row][lane*4+k] (ull).
    __shared__ __align__(16) ull   ubuf[PAIRS][2][2][128];
    __shared__ __align__(16) float Xp[PAIRS][2][2][PHI_OUT];  // X partials [pair][member][row][col]
    __shared__ __align__(16) ull   Xd[PAIRS][2][PHI_OUT];     // combined X, pre-dup'd (v,v)
    __shared__ unsigned s_max;
    __shared__ bool     s_last;

    const int tid  = threadIdx.x;
    const int w    = tid >> 5;
    const int lane = tid & 31;
    const int p    = w >> 1;      // pair id
    const int m    = w & 1;       // member id
    if (tid == 0) s_max = 0u;

    const int bA   = blockIdx.x * ROWS_PER_BLOCK + p * 2;  // pair's first row
    const int brow = bA + m;                               // this warp's output row

    // ---- stage: member m stages row m of its pair, SoA (coalesced LDG.128) ----
    {
        const float4* src = reinterpret_cast<const float4*>(x + (size_t)brow * XDIM);
        for (int n = lane; n < NBLK; n += 32) {
            const float4 v = src[n];
            xsT[p][m][0][n] = v.x;
            xsT[p][m][1][n] = v.y;
            xsT[p][m][2][n] = v.z;
            xsT[p][m][3][n] = v.w;
        }
    }
    __syncthreads();   // both rows staged; also orders s_max init

    // ---- layer-1 weights for member's 128 units u_k = 128m + lane + 32k,
    //      duplicated (w,w) ONCE at load time (loop body has zero dup cost) ----
    ull wd[4][4], bd[4];
    #pragma unroll
    for (int k = 0; k < 4; k++) {
        const int u = 128 * m + lane + 32 * k;
        bd[k] = dup2(__ldg(pb1 + u));
        #pragma unroll
        for (int r = 0; r < 4; r++)
            wd[r][k] = dup2(__ldg(pw1 + r * PHI_H + u));
    }

    float* Hsf = reinterpret_cast<float*>(&ubuf[p][0][0][0]);  // [row*256 + j]

    // ---- layer 1 + block-sum, n-packed: process blocks (2n, 2n+1) together.
    //      Operands are straight LDS.64 from SoA; H accumulated scalar. ----
    {
        float HA[4] = {0.f, 0.f, 0.f, 0.f};
        float HB[4] = {0.f, 0.f, 0.f, 0.f};
        const ull* xA0 = reinterpret_cast<const ull*>(&xsT[p][0][0][0]); // comp stride 34 ull
        const ull* xB0 = reinterpret_cast<const ull*>(&xsT[p][1][0][0]);
        #pragma unroll 3
        for (int np = 0; np < NPAIR; np++) {
            const ull axp = xA0[np],       ayp = xA0[34 + np];
            const ull azp = xA0[68 + np],  awp = xA0[102 + np];
            const ull bxp = xB0[np],       byp = xB0[34 + np];
            const ull bzp = xB0[68 + np],  bwp = xB0[102 + np];
            #pragma unroll
            for (int k = 0; k < 4; k++) {
                ull tA = ffma2(wd[0][k], axp, bd[k]);
                ull tB = ffma2(wd[0][k], bxp, bd[k]);
                tA = ffma2(wd[1][k], ayp, tA);
                tB = ffma2(wd[1][k], byp, tB);
                tA = ffma2(wd[2][k], azp, tA);
                tB = ffma2(wd[2][k], bzp, tB);
                tA = ffma2(wd[3][k], awp, tA);
                tB = ffma2(wd[3][k], bwp, tB);
                const float2 uA = unpack2(tA);
                const float2 uB = unpack2(tB);
                HA[k] += fmaxf(uA.x, 0.f) + fmaxf(uA.y, 0.f);
                HB[k] += fmaxf(uB.x, 0.f) + fmaxf(uB.y, 0.f);
            }
        }
        #pragma unroll
        for (int k = 0; k < 4; k++) {
            const int u = 128 * m + lane + 32 * k;
            Hsf[u]       = HA[k];
            Hsf[256 + u] = HB[k];
        }
    }
    __syncwarp();   // member reads only its own H range -> warp sync suffices

    // ---- X partial: sum over member's j range; lane owns cols (2*lane, 2*lane+1) ----
    {
        const int c0 = 2 * lane;
        const char* pw2c = reinterpret_cast<const char*>(pw2 + c0);
        ull accA0 = 0ull, accA1 = 0ull, accB0 = 0ull, accB1 = 0ull;
        const int jbeg = 128 * m;
        #pragma unroll 8
        for (int jo = 0; jo < 128; jo += 4) {
            const int j = jbeg + jo;
            const float4 hA = *reinterpret_cast<const float4*>(&Hsf[j]);
            const float4 hB = *reinterpret_cast<const float4*>(&Hsf[256 + j]);
            const size_t base = (size_t)j * (PHI_OUT * 4);
            const ull w0 = __ldg(reinterpret_cast<const ull*>(pw2c + base));
            const ull w1 = __ldg(reinterpret_cast<const ull*>(pw2c + base + PHI_OUT * 4));
            const ull w2 = __ldg(reinterpret_cast<const ull*>(pw2c + base + PHI_OUT * 8));
            const ull w3 = __ldg(reinterpret_cast<const ull*>(pw2c + base + PHI_OUT * 12));
            accA0 = ffma2(dup2(hA.x), w0, accA0);
            accB0 = ffma2(dup2(hB.x), w0, accB0);
            accA1 = ffma2(dup2(hA.y), w1, accA1);
            accB1 = ffma2(dup2(hB.y), w1, accB1);
            accA0 = ffma2(dup2(hA.z), w2, accA0);
            accB0 = ffma2(dup2(hB.z), w2, accB0);
            accA1 = ffma2(dup2(hA.w), w3, accA1);
            accB1 = ffma2(dup2(hB.w), w3, accB1);
        }
        const float2 uA = unpack2(add2(accA0, accA1));
        const float2 uB = unpack2(add2(accB0, accB1));
        Xp[p][m][0][c0]     = uA.x;
        Xp[p][m][0][c0 + 1] = uA.y;
        Xp[p][m][1][c0]     = uB.x;
        Xp[p][m][1][c0 + 1] = uB.y;
    }
    __syncthreads();

    // ---- combine X for row m; store PRE-DUPLICATED for rho1 LDS.64 broadcasts ----
    {
        const int c0 = 2 * lane;
        const float2 bv = __ldg(reinterpret_cast<const float2*>(pb2 + c0));
        const float xf0 = Xp[p][0][m][c0]     + Xp[p][1][m][c0]     + 66.f * bv.x;
        const float xf1 = Xp[p][0][m][c0 + 1] + Xp[p][1][m][c0 + 1] + 66.f * bv.y;
        Xd[p][m][c0]     = dup2(xf0);
        Xd[p][m][c0 + 1] = dup2(xf1);
    }
    __syncthreads();

    // ---- rho1 partial: member's i range [32m, 32m+32); lane owns 8 units j0..j0+7 ----
    const int j0 = 8 * lane;
    ull tA[4], tB[4];
    if (m == 0) {
        const ulonglong2 ra = __ldg(reinterpret_cast<const ulonglong2*>(rb1 + j0));
        const ulonglong2 rb = __ldg(reinterpret_cast<const ulonglong2*>(rb1 + j0 + 4));
        tA[0] = ra.x; tA[1] = ra.y; tA[2] = rb.x; tA[3] = rb.y;
        tB[0] = ra.x; tB[1] = ra.y; tB[2] = rb.x; tB[3] = rb.y;
    } else {
        tA[0] = tA[1] = tA[2] = tA[3] = 0ull;
        tB[0] = tB[1] = tB[2] = tB[3] = 0ull;
    }
    {
        const int ibeg = 32 * m;
        #pragma unroll 4
        for (int io = 0; io < 32; io++) {
            const int i = ibeg + io;
            const ull xA = Xd[p][0][i];   // pre-dup'd, single LDS.64 broadcast
            const ull xB = Xd[p][1][i];
            const ulonglong2 wa = __ldg(reinterpret_cast<const ulonglong2*>(rw1 + i * RHO_H + j0));
            const ulonglong2 wb = __ldg(reinterpret_cast<const ulonglong2*>(rw1 + i * RHO_H + j0 + 4));
            tA[0] = ffma2(xA, wa.x, tA[0]);  tB[0] = ffma2(xB, wa.x, tB[0]);
            tA[1] = ffma2(xA, wa.y, tA[1]);  tB[1] = ffma2(xB, wa.y, tB[1]);
            tA[2] = ffma2(xA, wb.x, tA[2]);  tB[2] = ffma2(xB, wb.x, tB[2]);
            tA[3] = ffma2(xA, wb.y, tA[3]);  tB[3] = ffma2(xB, wb.y, tB[3]);
        }
    }
    // store partials (pre-relu)
    {
        ulonglong2* dA = reinterpret_cast<ulonglong2*>(&ubuf[p][m][0][lane * 4]);
        dA[0] = make_ulonglong2(tA[0], tA[1]);
        dA[1] = make_ulonglong2(tA[2], tA[3]);
        ulonglong2* dB = reinterpret_cast<ulonglong2*>(&ubuf[p][m][1][lane * 4]);
        dB[0] = make_ulonglong2(tB[0], tB[1]);
        dB[1] = make_ulonglong2(tB[2], tB[3]);
    }
    __syncthreads();

    // ---- finish: warp handles its own row (= m). combine partials, relu, rho2 ----
    ull a2 = 0ull;
    {
        const ulonglong2 pa0 = *reinterpret_cast<const ulonglong2*>(&ubuf[p][0][m][lane * 4]);
        const ulonglong2 pa1 = *reinterpret_cast<const ulonglong2*>(&ubuf[p][0][m][lane * 4 + 2]);
        const ulonglong2 pb0 = *reinterpret_cast<const ulonglong2*>(&ubuf[p][1][m][lane * 4]);
        const ulonglong2 pb1v = *reinterpret_cast<const ulonglong2*>(&ubuf[p][1][m][lane * 4 + 2]);
        const ull t0 = add2(pa0.x, pb0.x);
        const ull t1 = add2(pa0.y, pb0.y);
        const ull t2 = add2(pa1.x, pb1v.x);
        const ull t3 = add2(pa1.y, pb1v.y);
        const ulonglong2 q01 = __ldg(reinterpret_cast<const ulonglong2*>(rw2 + 2 * j0));
        const ulonglong2 q23 = __ldg(reinterpret_cast<const ulonglong2*>(rw2 + 2 * j0 + 4));
        const ulonglong2 q45 = __ldg(reinterpret_cast<const ulonglong2*>(rw2 + 2 * j0 + 8));
        const ulonglong2 q67 = __ldg(reinterpret_cast<const ulonglong2*>(rw2 + 2 * j0 + 12));
        const float2 u0 = unpack2(t0), u1 = unpack2(t1);
        const float2 u2 = unpack2(t2), u3 = unpack2(t3);
        a2 = ffma2(dup2(fmaxf(u0.x, 0.f)), q01.x, a2);
        a2 = ffma2(dup2(fmaxf(u0.y, 0.f)), q01.y, a2);
        a2 = ffma2(dup2(fmaxf(u1.x, 0.f)), q23.x, a2);
        a2 = ffma2(dup2(fmaxf(u1.y, 0.f)), q23.y, a2);
        a2 = ffma2(dup2(fmaxf(u2.x, 0.f)), q45.x, a2);
        a2 = ffma2(dup2(fmaxf(u2.y, 0.f)), q45.y, a2);
        a2 = ffma2(dup2(fmaxf(u3.x, 0.f)), q67.x, a2);
        a2 = ffma2(dup2(fmaxf(u3.y, 0.f)), q67.y, a2);
    }

    // ---- barrier term for this warp's row: neighbors n = 2..65, 2 per lane ----
    float bx = 0.f, by = 0.f;
    #pragma unroll
    for (int q = 0; q < 2; q++) {
        const int n = 2 + lane + 32 * q;
        const float px = xsT[p][m][0][n], py = xsT[p][m][1][n];
        const float dm = sqrtf(px * px + py * py) - 0.15f;
        const float inv = 1.f / (dm * dm);
        bx -= px * inv;
        by -= py * inv;
    }

    // ---- warp butterfly reduce (a0, a1, bx, by) ----
    float a0, a1;
    { const float2 u = unpack2(a2); a0 = u.x; a1 = u.y; }
    #pragma unroll
    for (int off = 16; off > 0; off >>= 1) {
        a0 += __shfl_xor_sync(0xffffffff, a0, off);
        a1 += __shfl_xor_sync(0xffffffff, a1, off);
        bx += __shfl_xor_sync(0xffffffff, bx, off);
        by += __shfl_xor_sync(0xffffffff, by, off);
    }

    if (lane == 0) {
        const float r0 = 2.0f * tanhf(a0 + __ldg(rb2))     + bx;
        const float r1 = 2.0f * tanhf(a1 + __ldg(rb2 + 1)) + by;
        out[2 * brow]     = r0;
        out[2 * brow + 1] = r1;
        const unsigned k = max(fkey(r0), fkey(r1));
        atomicMax(&s_max, k);
    }
    __syncthreads();

    // ---- block max -> global; last block applies global rescale ----
    if (tid == 0) {
        atomicMax(&g_maxkey, s_max);
        __threadfence();
        const unsigned prev = atomicAdd(&g_done, 1u);
        s_last = (prev == (unsigned)(gridDim.x - 1));
    }
    __syncthreads();

    if (s_last) {
        __threadfence();
        const float mx    = kinv(atomicAdd(&g_maxkey, 0u));
        const float scale = 2.0f / mx;
        if (scale < 1.0f) {
            float4* o4 = reinterpret_cast<float4*>(out);
            for (int i = tid; i < BATCH * 2 / 4; i += blockDim.x) {
                float4 v = o4[i];
                v.x *= scale; v.y *= scale; v.z *= scale; v.w *= scale;
                o4[i] = v;
            }
        }
        __syncthreads();
        if (tid == 0) {
            g_maxkey = 0u;
            __threadfence();
            atomicExch(&g_done, 0u);
        }
    }
}

extern "C" void kernel_launch(void* const* d_in, const int* in_sizes, int n_in,
                              void* d_out, int out_size)
{
    const float* x   = (const float*)d_in[0];
    const float* pw1 = (const float*)d_in[1];
    const float* pb1 = (const float*)d_in[2];
    const float* pw2 = (const float*)d_in[3];
    const float* pb2 = (const float*)d_in[4];
    const float* rw1 = (const float*)d_in[5];
    const float* rb1 = (const float*)d_in[6];
    const float* rw2 = (const float*)d_in[7];
    const float* rb2 = (const float*)d_in[8];
    float* out = (float*)d_out;

    bn_main_kernel<<<NBLOCKS, 32 * WARPS_PER_BLOCK>>>(
        x, pw1, pb1, pw2, pb2, rw1, rb1, rw2, rb2, out);
}